// round 1
// baseline (speedup 1.0000x reference)
#include <cuda_runtime.h>
#include <cuda_bf16.h>

// Problem: x [64,224,224,32] f32; W_cls [32,4]; b_cls [4].
// out[b] = rot90(x[b], k[b]) with k[b] = argmax(mean_hw(x[b]) @ W + b).
//
// Stage 1: deterministic per-(batch,chunk) channel sums  (reads 411 MB)
// Stage 2: mean -> logits -> argmax per batch            (tiny)
// Stage 3: per-pixel gather rotation                     (reads+writes 822 MB)

#define BATCH 64
#define HW    224
#define PIX   (HW * HW)        // 50176 pixels per image
#define CH    32               // channels; one pixel = 128 B = 8 float4
#define NCHUNK 49              // 49 * 1024 = 50176
#define CHUNK_PIX 1024

// Scratch (no device allocation allowed) — fully overwritten every call.
__device__ float4 g_partial[BATCH * NCHUNK * 8];   // per-chunk channel sums
__device__ int    g_k[BATCH];

// ---------------- Stage 1: chunked channel-sum reduction -------------------
// Block = 256 threads handles one (batch, chunk) of 1024 pixels.
// 8 threads per pixel (one float4 each). Deterministic: shuffle tree + fixed
// order smem combine; no atomics.
__global__ void __launch_bounds__(256) stage1_reduce(const float4* __restrict__ x) {
    int blk   = blockIdx.x;
    int b     = blk / NCHUNK;
    int chunk = blk - b * NCHUNK;
    int t     = threadIdx.x;
    int lane  = t & 31;
    int warp  = t >> 5;
    int q     = t & 7;                 // float4 slot within pixel (channel group)

    // base float4 index of this chunk
    unsigned base = ((unsigned)b * PIX + (unsigned)chunk * CHUNK_PIX) * 8u;

    float4 s = make_float4(0.f, 0.f, 0.f, 0.f);
#pragma unroll 4
    for (int it = 0; it < 32; ++it) {
        unsigned pix = (unsigned)(it * 32 + (t >> 3));
        float4 v = __ldg(&x[base + pix * 8u + q]);
        s.x += v.x; s.y += v.y; s.z += v.z; s.w += v.w;
    }
    // combine lanes that share q (differ in bits 3,4 of lane): xor 8, xor 16
#pragma unroll
    for (int off = 8; off <= 16; off <<= 1) {
        s.x += __shfl_xor_sync(0xffffffffu, s.x, off);
        s.y += __shfl_xor_sync(0xffffffffu, s.y, off);
        s.z += __shfl_xor_sync(0xffffffffu, s.z, off);
        s.w += __shfl_xor_sync(0xffffffffu, s.w, off);
    }

    __shared__ float4 sm[8][8];        // [warp][q]
    if (lane < 8) sm[warp][lane] = s;
    __syncthreads();

    if (t < 8) {
        float4 acc = sm[0][t];
#pragma unroll
        for (int w = 1; w < 8; ++w) {
            float4 v = sm[w][t];
            acc.x += v.x; acc.y += v.y; acc.z += v.z; acc.w += v.w;
        }
        g_partial[(b * NCHUNK + chunk) * 8 + t] = acc;
    }
}

// ---------------- Stage 2: mean -> logits -> argmax ------------------------
// Grid = 64 blocks of 32 threads; thread c owns channel c.
__global__ void stage2_argmax(const float* __restrict__ W_cls,
                              const float* __restrict__ b_cls) {
    int b = blockIdx.x;
    int c = threadIdx.x;               // 0..31
    int q = c >> 2;                    // which float4 slot holds channel c
    int r = c & 3;

    float s = 0.f;
    for (int ch = 0; ch < NCHUNK; ++ch) {
        float4 v = g_partial[(b * NCHUNK + ch) * 8 + q];
        s += (r == 0) ? v.x : (r == 1) ? v.y : (r == 2) ? v.z : v.w;
    }
    __shared__ float mean[CH];
    mean[c] = s * (1.0f / (float)PIX);
    __syncthreads();

    if (c == 0) {
        float best = -3.402823466e38f;
        int bi = 0;
#pragma unroll
        for (int o = 0; o < 4; ++o) {
            float l = b_cls[o];
#pragma unroll
            for (int cc = 0; cc < CH; ++cc)
                l += mean[cc] * W_cls[cc * 4 + o];
            if (l > best) { best = l; bi = o; }   // first-max tie-break (jnp.argmax)
        }
        g_k[b] = bi;
    }
}

// ---------------- Stage 3: per-pixel gather rotation -----------------------
// One float4 (4 channels) per thread. Writes coalesced; reads 128B-granular.
// rot90 CCW mapping (out[i,j] = src[si,sj]):
//   k=0: (i, j)        k=1: (j, W-1-i)
//   k=2: (H-1-i,W-1-j) k=3: (H-1-j, i)
__global__ void __launch_bounds__(256) stage3_rotate(const float4* __restrict__ x,
                                                     float4* __restrict__ out,
                                                     unsigned total4) {
    unsigned idx = blockIdx.x * 256u + threadIdx.x;
    if (idx >= total4) return;

    unsigned q = idx & 7u;
    unsigned p = idx >> 3;             // pixel linear index
    unsigned j = p % HW;
    unsigned rbi = p / HW;
    unsigned i = rbi % HW;
    unsigned b = rbi / HW;

    int k = g_k[b];
    int si, sj;
    switch (k) {
        case 0:  si = (int)i;            sj = (int)j;            break;
        case 1:  si = (int)j;            sj = HW - 1 - (int)i;   break;
        case 2:  si = HW - 1 - (int)i;   sj = HW - 1 - (int)j;   break;
        default: si = HW - 1 - (int)j;   sj = (int)i;            break;
    }
    unsigned sidx = (((b * HW + (unsigned)si) * HW) + (unsigned)sj) * 8u + q;
    out[idx] = __ldg(&x[sidx]);
}

extern "C" void kernel_launch(void* const* d_in, const int* in_sizes, int n_in,
                              void* d_out, int out_size) {
    const float4* x     = (const float4*)d_in[0];
    const float*  W_cls = (const float*)d_in[1];
    const float*  b_cls = (const float*)d_in[2];
    float4*       out   = (float4*)d_out;

    // Stage 1: 64 batches * 49 chunks
    stage1_reduce<<<BATCH * NCHUNK, 256>>>(x);

    // Stage 2: logits + argmax
    stage2_argmax<<<BATCH, 32>>>(W_cls, b_cls);

    // Stage 3: rotation gather. total float4 = 64*224*224*8 = 25,690,112
    unsigned total4 = (unsigned)BATCH * PIX * 8u;
    unsigned nblk = (total4 + 255u) / 256u;   // 100352
    stage3_rotate<<<nblk, 256>>>(x, out, total4);
}